// round 1
// baseline (speedup 1.0000x reference)
#include <cuda_runtime.h>
#include <cuda_bf16.h>

// Problem constants (fixed by setup_inputs): b=48, n=512, DIM=96, HEADS=6, hd=16, h=w=d=8
#define NB 48
#define NTOK 512
#define NHEAD 6
#define HD 16
#define POSD 6
#define KSTR 20          // smem row stride (floats) for conflict-free LDS.128
#define SCALE 0.25f      // 16^-0.5
#define NPOS 43          // only indices 0..42 of the pos table are ever used

__device__ float g_pos[2 * NPOS * NHEAD];                 // [i][m][head]
__device__ float g_x1[NB * NHEAD * NTOK * HD];            // pass-1 output scratch

// ---------------------------------------------------------------------------
// Tiny pos-MLP: 2 tables x 43 rows, each row: 3->6, (LN,relu,6->6) x2, LN,relu,6->6heads
// ---------------------------------------------------------------------------
__device__ __forceinline__ void ln6(float* x, const float* g, const float* b) {
    float mu = 0.f;
#pragma unroll
    for (int j = 0; j < 6; ++j) mu += x[j];
    mu *= (1.f / 6.f);
    float var = 0.f;
#pragma unroll
    for (int j = 0; j < 6; ++j) { float d = x[j] - mu; var += d * d; }
    var *= (1.f / 6.f);
    float inv = rsqrtf(var + 1e-5f);
#pragma unroll
    for (int j = 0; j < 6; ++j) x[j] = (x[j] - mu) * inv * g[j] + b[j];
}

__global__ void pos_mlp_kernel(
    const float* __restrict__ W0, const float* __restrict__ B0,
    const float* __restrict__ G1, const float* __restrict__ Be1,
    const float* __restrict__ W1, const float* __restrict__ B1,
    const float* __restrict__ G2, const float* __restrict__ Be2,
    const float* __restrict__ W2, const float* __restrict__ B2,
    const float* __restrict__ G3, const float* __restrict__ Be3,
    const float* __restrict__ W3, const float* __restrict__ B3)
{
    int tid = threadIdx.x;
    int i = tid >> 6;          // table 0 or 1
    int m = tid & 63;
    if (m >= NPOS || i >= 2) return;

    // biases row m (m < 225 -> bh_idx = 0): bh=-7, bw=m/15-7, bd=m%15-7
    float bh = -7.f;
    float bw = (float)(m / 15) - 7.f;
    float bd = (float)(m % 15) - 7.f;

    float x[6], y[6];
#pragma unroll
    for (int j = 0; j < 6; ++j) {
        const float* w = W0 + (i * 6 + j) * 3;
        x[j] = bh * w[0] + bw * w[1] + bd * w[2] + B0[i * 6 + j];
    }
    ln6(x, G1 + i * 6, Be1 + i * 6);
#pragma unroll
    for (int j = 0; j < 6; ++j) x[j] = fmaxf(x[j], 0.f);
#pragma unroll
    for (int j = 0; j < 6; ++j) {
        const float* w = W1 + (i * 6 + j) * 6;
        float s = B1[i * 6 + j];
#pragma unroll
        for (int k = 0; k < 6; ++k) s += x[k] * w[k];
        y[j] = s;
    }
    ln6(y, G2 + i * 6, Be2 + i * 6);
#pragma unroll
    for (int j = 0; j < 6; ++j) y[j] = fmaxf(y[j], 0.f);
#pragma unroll
    for (int j = 0; j < 6; ++j) {
        const float* w = W2 + (i * 6 + j) * 6;
        float s = B2[i * 6 + j];
#pragma unroll
        for (int k = 0; k < 6; ++k) s += y[k] * w[k];
        x[j] = s;
    }
    ln6(x, G3 + i * 6, Be3 + i * 6);
#pragma unroll
    for (int j = 0; j < 6; ++j) x[j] = fmaxf(x[j], 0.f);
#pragma unroll
    for (int hh = 0; hh < NHEAD; ++hh) {
        const float* w = W3 + (i * NHEAD + hh) * 6;
        float s = B3[i * NHEAD + hh];
#pragma unroll
        for (int k = 0; k < 6; ++k) s += x[k] * w[k];
        g_pos[(i * NPOS + m) * NHEAD + hh] = s;
    }
}

// ---------------------------------------------------------------------------
// Fused attention pass: one CTA per (batch, head). K,V staged in smem.
// Softmax without max subtraction (logits are O(1) here) -> single fused pass.
// Bias: sPos[scq - scm], scq/scm = digit-sum of token index + offsets.
// ---------------------------------------------------------------------------
__device__ __forceinline__ int digitsum(int t) {
    return (t >> 6) + ((t >> 3) & 7) + (t & 7);
}

__global__ __launch_bounds__(256, 2) void attn_kernel(
    const float* __restrict__ Qg, int qb, int qh, int qt,
    const float* __restrict__ Kg, int kb, int kh, int kt,
    const float* __restrict__ Vg, int vb, int vh, int vt,
    float* __restrict__ Og, int ob, int oh, int ot,
    const float* __restrict__ posG)
{
    extern __shared__ float sm[];
    float* sK = sm;                          // [512][KSTR]
    float* sV = sm + NTOK * KSTR;            // [512][KSTR]
    float* sPos = sm + 2 * NTOK * KSTR;      // [43]

    int bh = blockIdx.x;
    int b = bh / NHEAD, h = bh % NHEAD;
    const float* Q = Qg + (long)b * qb + h * qh;
    const float* K = Kg + (long)b * kb + h * kh;
    const float* V = Vg + (long)b * vb + h * vh;
    float* O = Og + (long)b * ob + h * oh;

    int tid = threadIdx.x;
    if (tid < NPOS) sPos[tid] = posG[tid * NHEAD + h];

    // cooperative load of K and V into padded smem (float4 granular)
    for (int e = tid; e < NTOK * 4; e += 256) {
        int t = e >> 2;
        int c = (e & 3) * 4;
        float4 kv = *reinterpret_cast<const float4*>(K + t * kt + c);
        *reinterpret_cast<float4*>(&sK[t * KSTR + c]) = kv;
        float4 vv = *reinterpret_cast<const float4*>(V + t * vt + c);
        *reinterpret_cast<float4*>(&sV[t * KSTR + c]) = vv;
    }
    __syncthreads();

    int warp = tid >> 5, lane = tid & 31;

    for (int it = 0; it < 32; ++it) {
        int r0 = warp * 64 + it * 2;
        int r1 = r0 + 1;

        float q0[HD], q1[HD];
        {
            const float* Qr0 = Q + r0 * qt;
            const float* Qr1 = Q + r1 * qt;
#pragma unroll
            for (int c = 0; c < HD; c += 4) {
                float4 a = *reinterpret_cast<const float4*>(Qr0 + c);
                q0[c] = a.x * SCALE; q0[c + 1] = a.y * SCALE;
                q0[c + 2] = a.z * SCALE; q0[c + 3] = a.w * SCALE;
                float4 bq = *reinterpret_cast<const float4*>(Qr1 + c);
                q1[c] = bq.x * SCALE; q1[c + 1] = bq.y * SCALE;
                q1[c + 2] = bq.z * SCALE; q1[c + 3] = bq.w * SCALE;
            }
        }
        int sc0 = digitsum(r0) + 21;
        int sc1 = digitsum(r1) + 21;

        float acc0[HD], acc1[HD];
#pragma unroll
        for (int c = 0; c < HD; ++c) { acc0[c] = 0.f; acc1[c] = 0.f; }
        float sum0 = 0.f, sum1 = 0.f;

#pragma unroll 2
        for (int kk = 0; kk < 16; ++kk) {
            int m = lane + (kk << 5);
            const float* kp = &sK[m * KSTR];
            float kr[HD];
#pragma unroll
            for (int c = 0; c < HD; c += 4) {
                float4 a = *reinterpret_cast<const float4*>(kp + c);
                kr[c] = a.x; kr[c + 1] = a.y; kr[c + 2] = a.z; kr[c + 3] = a.w;
            }
            float d0 = 0.f, d1 = 0.f;
#pragma unroll
            for (int c = 0; c < HD; ++c) {
                d0 += q0[c] * kr[c];
                d1 += q1[c] * kr[c];
            }
            int scm = digitsum(m);
            float p0 = __expf(d0 + sPos[sc0 - scm]);
            float p1 = __expf(d1 + sPos[sc1 - scm]);
            sum0 += p0; sum1 += p1;

            const float* vp = &sV[m * KSTR];
#pragma unroll
            for (int c = 0; c < HD; c += 4) {
                float4 a = *reinterpret_cast<const float4*>(vp + c);
                acc0[c]     += p0 * a.x; acc1[c]     += p1 * a.x;
                acc0[c + 1] += p0 * a.y; acc1[c + 1] += p1 * a.y;
                acc0[c + 2] += p0 * a.z; acc1[c + 2] += p1 * a.z;
                acc0[c + 3] += p0 * a.w; acc1[c + 3] += p1 * a.w;
            }
        }

        // reduce sums across warp
#pragma unroll
        for (int off = 16; off > 0; off >>= 1) {
            sum0 += __shfl_xor_sync(0xffffffffu, sum0, off);
            sum1 += __shfl_xor_sync(0xffffffffu, sum1, off);
        }
        float inv0 = 1.f / sum0;
        float inv1 = 1.f / sum1;

        // reduce each channel; lane c ends up owning channel c
        float o0 = 0.f, o1 = 0.f;
#pragma unroll
        for (int c = 0; c < HD; ++c) {
            float t0 = acc0[c], t1 = acc1[c];
#pragma unroll
            for (int off = 16; off > 0; off >>= 1) {
                t0 += __shfl_xor_sync(0xffffffffu, t0, off);
                t1 += __shfl_xor_sync(0xffffffffu, t1, off);
            }
            if (lane == c) { o0 = t0; o1 = t1; }
        }
        if (lane < HD) {
            O[r0 * ot + lane] = o0 * inv0;
            O[r1 * ot + lane] = o1 * inv1;
        }
    }
}

// ---------------------------------------------------------------------------
extern "C" void kernel_launch(void* const* d_in, const int* in_sizes, int n_in,
                              void* d_out, int out_size)
{
    const float* qkv  = (const float*)d_in[0];   // (48,512,288)
    const float* grid = (const float*)d_in[1];   // (48,512,96)
    const float* W0  = (const float*)d_in[2];
    const float* B0  = (const float*)d_in[3];
    const float* G1  = (const float*)d_in[4];
    const float* Be1 = (const float*)d_in[5];
    const float* W1  = (const float*)d_in[6];
    const float* B1  = (const float*)d_in[7];
    const float* G2  = (const float*)d_in[8];
    const float* Be2 = (const float*)d_in[9];
    const float* W2  = (const float*)d_in[10];
    const float* B2  = (const float*)d_in[11];
    const float* G3  = (const float*)d_in[12];
    const float* Be3 = (const float*)d_in[13];
    const float* W3  = (const float*)d_in[14];
    const float* B3  = (const float*)d_in[15];
    float* out = (float*)d_out;

    float* pos_ptr = nullptr;
    float* x1_ptr = nullptr;
    cudaGetSymbolAddress((void**)&pos_ptr, g_pos);
    cudaGetSymbolAddress((void**)&x1_ptr, g_x1);

    const int SMEM = (2 * NTOK * KSTR + 64) * sizeof(float);
    cudaFuncSetAttribute(attn_kernel, cudaFuncAttributeMaxDynamicSharedMemorySize, SMEM);

    pos_mlp_kernel<<<1, 128>>>(W0, B0, G1, Be1, W1, B1, G2, Be2, W2, B2, G3, Be3, W3, B3);

    // Pass 1: affine(grid, k, v, rpb0) -> g_x1 [b][h][t][16]
    attn_kernel<<<NB * NHEAD, 256, SMEM>>>(
        grid,          NTOK * 96,  HD, 96,            // Q = grid
        qkv + 96,      NTOK * 288, HD, 288,           // K = qkv[:, :, 96..]
        qkv + 192,     NTOK * 288, HD, 288,           // V = qkv[:, :, 192..]
        x1_ptr,        NHEAD * NTOK * HD, NTOK * HD, HD,
        pos_ptr);                                      // table 0

    // Pass 2: affine(q, grid, x1, rpb1) -> out (b, n, 96)
    attn_kernel<<<NB * NHEAD, 256, SMEM>>>(
        qkv,           NTOK * 288, HD, 288,           // Q = qkv[:, :, 0..]
        grid,          NTOK * 96,  HD, 96,            // K = grid
        x1_ptr,        NHEAD * NTOK * HD, NTOK * HD, HD,  // V = x1
        out,           NTOK * 96,  HD, 96,
        pos_ptr + NPOS * NHEAD);                       // table 1
}

// round 3
// speedup vs baseline: 1.6985x; 1.6985x over previous
#include <cuda_runtime.h>
#include <cuda_bf16.h>

// Problem constants (fixed by setup_inputs): b=48, n=512, DIM=96, HEADS=6, hd=16, h=w=d=8
#define NB 48
#define NTOK 512
#define NHEAD 6
#define HD 16
#define KSTR 20          // smem row stride (floats); keeps 16B alignment, pads staging stores
#define SCALE 0.25f      // 16^-0.5
#define NPOS 43          // only indices 0..42 of the pos table are ever used

typedef unsigned long long ULL;

__device__ float g_pos[2 * NPOS * NHEAD];                 // [i][m][head]
__device__ float g_x1[NB * NHEAD * NTOK * HD];            // pass-1 output scratch

// ---------------- packed f32x2 helpers (sm_103a FFMA2 path, PTX-only) ------
__device__ __forceinline__ ULL fma2(ULL a, ULL b, ULL c) {
    ULL d; asm("fma.rn.f32x2 %0,%1,%2,%3;" : "=l"(d) : "l"(a), "l"(b), "l"(c)); return d;
}
__device__ __forceinline__ ULL mul2(ULL a, ULL b) {
    ULL d; asm("mul.rn.f32x2 %0,%1,%2;" : "=l"(d) : "l"(a), "l"(b)); return d;
}
__device__ __forceinline__ ULL add2(ULL a, ULL b) {
    ULL d; asm("add.rn.f32x2 %0,%1,%2;" : "=l"(d) : "l"(a), "l"(b)); return d;
}
__device__ __forceinline__ ULL pack2(float lo, float hi) {
    ULL r; asm("mov.b64 %0,{%1,%2};" : "=l"(r) : "f"(lo), "f"(hi)); return r;
}
__device__ __forceinline__ float2 unpack2(ULL v) {
    float2 f; asm("mov.b64 {%0,%1},%2;" : "=f"(f.x), "=f"(f.y) : "l"(v)); return f;
}

// ---------------------------------------------------------------------------
// Tiny pos-MLP: 2 tables x 43 rows
// ---------------------------------------------------------------------------
__device__ __forceinline__ void ln6(float* x, const float* g, const float* b) {
    float mu = 0.f;
#pragma unroll
    for (int j = 0; j < 6; ++j) mu += x[j];
    mu *= (1.f / 6.f);
    float var = 0.f;
#pragma unroll
    for (int j = 0; j < 6; ++j) { float d = x[j] - mu; var += d * d; }
    var *= (1.f / 6.f);
    float inv = rsqrtf(var + 1e-5f);
#pragma unroll
    for (int j = 0; j < 6; ++j) x[j] = (x[j] - mu) * inv * g[j] + b[j];
}

__global__ void pos_mlp_kernel(
    const float* __restrict__ W0, const float* __restrict__ B0,
    const float* __restrict__ G1, const float* __restrict__ Be1,
    const float* __restrict__ W1, const float* __restrict__ B1,
    const float* __restrict__ G2, const float* __restrict__ Be2,
    const float* __restrict__ W2, const float* __restrict__ B2,
    const float* __restrict__ G3, const float* __restrict__ Be3,
    const float* __restrict__ W3, const float* __restrict__ B3)
{
    int tid = threadIdx.x;
    int i = tid >> 6;          // table 0 or 1
    int m = tid & 63;
    if (m >= NPOS || i >= 2) return;

    float bh = -7.f;
    float bw = (float)(m / 15) - 7.f;
    float bd = (float)(m % 15) - 7.f;

    float x[6], y[6];
#pragma unroll
    for (int j = 0; j < 6; ++j) {
        const float* w = W0 + (i * 6 + j) * 3;
        x[j] = bh * w[0] + bw * w[1] + bd * w[2] + B0[i * 6 + j];
    }
    ln6(x, G1 + i * 6, Be1 + i * 6);
#pragma unroll
    for (int j = 0; j < 6; ++j) x[j] = fmaxf(x[j], 0.f);
#pragma unroll
    for (int j = 0; j < 6; ++j) {
        const float* w = W1 + (i * 6 + j) * 6;
        float s = B1[i * 6 + j];
#pragma unroll
        for (int k = 0; k < 6; ++k) s += x[k] * w[k];
        y[j] = s;
    }
    ln6(y, G2 + i * 6, Be2 + i * 6);
#pragma unroll
    for (int j = 0; j < 6; ++j) y[j] = fmaxf(y[j], 0.f);
#pragma unroll
    for (int j = 0; j < 6; ++j) {
        const float* w = W2 + (i * 6 + j) * 6;
        float s = B2[i * 6 + j];
#pragma unroll
        for (int k = 0; k < 6; ++k) s += y[k] * w[k];
        x[j] = s;
    }
    ln6(x, G3 + i * 6, Be3 + i * 6);
#pragma unroll
    for (int j = 0; j < 6; ++j) x[j] = fmaxf(x[j], 0.f);
#pragma unroll
    for (int hh = 0; hh < NHEAD; ++hh) {
        const float* w = W3 + (i * NHEAD + hh) * 6;
        float s = B3[i * NHEAD + hh];
#pragma unroll
        for (int k = 0; k < 6; ++k) s += x[k] * w[k];
        g_pos[(i * NPOS + m) * NHEAD + hh] = s;
    }
}

// ---------------------------------------------------------------------------
// Fused attention pass: one CTA per (batch, head). K,V staged in smem.
// Each lane owns 2 full query rows; keys are walked with BROADCAST smem
// loads (1 crossbar phase per LDS.128), accumulators stay per-lane (no
// shuffles). All inner math is packed f32x2 (FFMA2).
// ---------------------------------------------------------------------------
__device__ __forceinline__ int digitsum(int t) {
    return (t >> 6) + ((t >> 3) & 7) + (t & 7);
}

__global__ __launch_bounds__(256, 2) void attn_kernel(
    const float* __restrict__ Qg, int qb, int qh, int qt,
    const float* __restrict__ Kg, int kb, int kh, int kt,
    const float* __restrict__ Vg, int vb, int vh, int vt,
    float* __restrict__ Og, int ob, int oh, int ot,
    const float* __restrict__ posG)
{
    extern __shared__ float sm[];
    float* sK = sm;                          // [512][KSTR]
    float* sV = sm + NTOK * KSTR;            // [512][KSTR]
    float* sPos = sm + 2 * NTOK * KSTR;      // [43]

    int bh = blockIdx.x;
    int b = bh / NHEAD, h = bh % NHEAD;
    const float* Q = Qg + (long)b * qb + h * qh;
    const float* K = Kg + (long)b * kb + h * kh;
    const float* V = Vg + (long)b * vb + h * vh;
    float* O = Og + (long)b * ob + h * oh;

    int tid = threadIdx.x;
    if (tid < NPOS) sPos[tid] = posG[tid * NHEAD + h];

    // cooperative load of K and V into padded smem (float4 granular)
    for (int e = tid; e < NTOK * 4; e += 256) {
        int t = e >> 2;
        int c = (e & 3) * 4;
        float4 kv = *reinterpret_cast<const float4*>(K + t * kt + c);
        *reinterpret_cast<float4*>(&sK[t * KSTR + c]) = kv;
        float4 vv = *reinterpret_cast<const float4*>(V + t * vt + c);
        *reinterpret_cast<float4*>(&sV[t * KSTR + c]) = vv;
    }
    __syncthreads();

    int warp = tid >> 5, lane = tid & 31;
    int r0 = warp * 64 + lane;
    int r1 = r0 + 32;

    // load + scale the two query rows, packed as f32x2
    ULL q0[8], q1[8];
    {
        ULL s2 = pack2(SCALE, SCALE);
        const ulonglong2* Q0p = reinterpret_cast<const ulonglong2*>(Q + r0 * qt);
        const ulonglong2* Q1p = reinterpret_cast<const ulonglong2*>(Q + r1 * qt);
#pragma unroll
        for (int j = 0; j < 4; ++j) {
            ulonglong2 t0 = Q0p[j];
            q0[2 * j] = mul2(t0.x, s2); q0[2 * j + 1] = mul2(t0.y, s2);
            ulonglong2 t1 = Q1p[j];
            q1[2 * j] = mul2(t1.x, s2); q1[2 * j + 1] = mul2(t1.y, s2);
        }
    }
    int sc0 = digitsum(r0) + 21;
    int sc1 = digitsum(r1) + 21;

    ULL acc0[8], acc1[8];
#pragma unroll
    for (int j = 0; j < 8; ++j) { acc0[j] = 0ull; acc1[j] = 0ull; }
    ULL sum01 = 0ull;   // (sum0, sum1) packed

#pragma unroll 2
    for (int m = 0; m < NTOK; ++m) {
        // broadcast K row (all lanes same address -> 1 phase per LDS.128)
        const ulonglong2* kp = reinterpret_cast<const ulonglong2*>(&sK[m * KSTR]);
        ulonglong2 a0 = kp[0], a1 = kp[1], a2 = kp[2], a3 = kp[3];

        ULL d0a = 0ull, d0b = 0ull, d1a = 0ull, d1b = 0ull;
        d0a = fma2(q0[0], a0.x, d0a); d1a = fma2(q1[0], a0.x, d1a);
        d0b = fma2(q0[1], a0.y, d0b); d1b = fma2(q1[1], a0.y, d1b);
        d0a = fma2(q0[2], a1.x, d0a); d1a = fma2(q1[2], a1.x, d1a);
        d0b = fma2(q0[3], a1.y, d0b); d1b = fma2(q1[3], a1.y, d1b);
        d0a = fma2(q0[4], a2.x, d0a); d1a = fma2(q1[4], a2.x, d1a);
        d0b = fma2(q0[5], a2.y, d0b); d1b = fma2(q1[5], a2.y, d1b);
        d0a = fma2(q0[6], a3.x, d0a); d1a = fma2(q1[6], a3.x, d1a);
        d0b = fma2(q0[7], a3.y, d0b); d1b = fma2(q1[7], a3.y, d1b);

        float2 e0 = unpack2(add2(d0a, d0b));
        float2 e1 = unpack2(add2(d1a, d1b));

        int scm = digitsum(m);
        float p0 = __expf(e0.x + e0.y + sPos[sc0 - scm]);
        float p1 = __expf(e1.x + e1.y + sPos[sc1 - scm]);
        sum01 = add2(sum01, pack2(p0, p1));

        ULL pp0 = pack2(p0, p0), pp1 = pack2(p1, p1);
        const ulonglong2* vp = reinterpret_cast<const ulonglong2*>(&sV[m * KSTR]);
        ulonglong2 b0 = vp[0], b1 = vp[1], b2 = vp[2], b3 = vp[3];
        acc0[0] = fma2(pp0, b0.x, acc0[0]); acc1[0] = fma2(pp1, b0.x, acc1[0]);
        acc0[1] = fma2(pp0, b0.y, acc0[1]); acc1[1] = fma2(pp1, b0.y, acc1[1]);
        acc0[2] = fma2(pp0, b1.x, acc0[2]); acc1[2] = fma2(pp1, b1.x, acc1[2]);
        acc0[3] = fma2(pp0, b1.y, acc0[3]); acc1[3] = fma2(pp1, b1.y, acc1[3]);
        acc0[4] = fma2(pp0, b2.x, acc0[4]); acc1[4] = fma2(pp1, b2.x, acc1[4]);
        acc0[5] = fma2(pp0, b2.y, acc0[5]); acc1[5] = fma2(pp1, b2.y, acc1[5]);
        acc0[6] = fma2(pp0, b3.x, acc0[6]); acc1[6] = fma2(pp1, b3.x, acc1[6]);
        acc0[7] = fma2(pp0, b3.y, acc0[7]); acc1[7] = fma2(pp1, b3.y, acc1[7]);
    }

    float2 s = unpack2(sum01);
    float inv0 = 1.f / s.x;
    float inv1 = 1.f / s.y;
    ULL iv0 = pack2(inv0, inv0), iv1 = pack2(inv1, inv1);

    ulonglong2* O0 = reinterpret_cast<ulonglong2*>(O + r0 * ot);
    ulonglong2* O1 = reinterpret_cast<ulonglong2*>(O + r1 * ot);
#pragma unroll
    for (int j = 0; j < 4; ++j) {
        ulonglong2 w0, w1;
        w0.x = mul2(acc0[2 * j], iv0); w0.y = mul2(acc0[2 * j + 1], iv0);
        w1.x = mul2(acc1[2 * j], iv1); w1.y = mul2(acc1[2 * j + 1], iv1);
        O0[j] = w0;
        O1[j] = w1;
    }
}

// ---------------------------------------------------------------------------
extern "C" void kernel_launch(void* const* d_in, const int* in_sizes, int n_in,
                              void* d_out, int out_size)
{
    const float* qkv  = (const float*)d_in[0];   // (48,512,288)
    const float* grid = (const float*)d_in[1];   // (48,512,96)
    const float* W0  = (const float*)d_in[2];
    const float* B0  = (const float*)d_in[3];
    const float* G1  = (const float*)d_in[4];
    const float* Be1 = (const float*)d_in[5];
    const float* W1  = (const float*)d_in[6];
    const float* B1  = (const float*)d_in[7];
    const float* G2  = (const float*)d_in[8];
    const float* Be2 = (const float*)d_in[9];
    const float* W2  = (const float*)d_in[10];
    const float* B2  = (const float*)d_in[11];
    const float* G3  = (const float*)d_in[12];
    const float* Be3 = (const float*)d_in[13];
    const float* W3  = (const float*)d_in[14];
    const float* B3  = (const float*)d_in[15];
    float* out = (float*)d_out;

    float* pos_ptr = nullptr;
    float* x1_ptr = nullptr;
    cudaGetSymbolAddress((void**)&pos_ptr, g_pos);
    cudaGetSymbolAddress((void**)&x1_ptr, g_x1);

    const int SMEM = (2 * NTOK * KSTR + 64) * sizeof(float);
    cudaFuncSetAttribute(attn_kernel, cudaFuncAttributeMaxDynamicSharedMemorySize, SMEM);

    pos_mlp_kernel<<<1, 128>>>(W0, B0, G1, Be1, W1, B1, G2, Be2, W2, B2, G3, Be3, W3, B3);

    // Pass 1: affine(grid, k, v, rpb0) -> g_x1 [b][h][t][16]
    attn_kernel<<<NB * NHEAD, 256, SMEM>>>(
        grid,          NTOK * 96,  HD, 96,            // Q = grid
        qkv + 96,      NTOK * 288, HD, 288,           // K = qkv[:, :, 96..]
        qkv + 192,     NTOK * 288, HD, 288,           // V = qkv[:, :, 192..]
        x1_ptr,        NHEAD * NTOK * HD, NTOK * HD, HD,
        pos_ptr);                                      // table 0

    // Pass 2: affine(q, grid, x1, rpb1) -> out (b, n, 96)
    attn_kernel<<<NB * NHEAD, 256, SMEM>>>(
        qkv,           NTOK * 288, HD, 288,           // Q = qkv[:, :, 0..]
        grid,          NTOK * 96,  HD, 96,            // K = grid
        x1_ptr,        NHEAD * NTOK * HD, NTOK * HD, HD,  // V = x1
        out,           NTOK * 96,  HD, 96,
        pos_ptr + NPOS * NHEAD);                       // table 1
}

// round 4
// speedup vs baseline: 6.0968x; 3.5894x over previous
#include <cuda_runtime.h>
#include <cuda_bf16.h>

// Problem constants: b=48, n=512, DIM=96, HEADS=6, hd=16, h=w=d=8
#define NB 48
#define NTOK 512
#define NHEAD 6
#define HD 16
#define NPOS 43
#define L2E 1.4426950408889634f
#define QS (0.25f * L2E)     // attention scale folded with log2(e)

__device__ float g_pos[2 * NPOS * NHEAD];        // [i][m][head]
__device__ float g_x1[NB * NHEAD * NTOK * HD];   // pass-1 output scratch

// ---------------------------------------------------------------------------
// helpers
// ---------------------------------------------------------------------------
__device__ __forceinline__ unsigned f2tf32(float x) {
    unsigned r; asm("cvt.rna.tf32.f32 %0,%1;" : "=r"(r) : "f"(x)); return r;
}
__device__ __forceinline__ float ex2(float x) {
    float r; asm("ex2.approx.ftz.f32 %0,%1;" : "=f"(r) : "f"(x)); return r;
}
__device__ __forceinline__ void mma_tf32(
    float& c0, float& c1, float& c2, float& c3,
    unsigned a0, unsigned a1, unsigned a2, unsigned a3,
    unsigned b0, unsigned b1)
{
    asm("mma.sync.aligned.m16n8k8.row.col.f32.tf32.tf32.f32 "
        "{%0,%1,%2,%3},{%4,%5,%6,%7},{%8,%9},{%0,%1,%2,%3};"
        : "+f"(c0), "+f"(c1), "+f"(c2), "+f"(c3)
        : "r"(a0), "r"(a1), "r"(a2), "r"(a3), "r"(b0), "r"(b1));
}
__device__ __forceinline__ int ds9(int t) {   // base-8 digit sum of 9-bit index
    return (t >> 6) + ((t >> 3) & 7) + (t & 7);
}

// ---------------------------------------------------------------------------
// Tiny pos-MLP: 2 tables x 43 rows
// ---------------------------------------------------------------------------
__device__ __forceinline__ void ln6(float* x, const float* g, const float* b) {
    float mu = 0.f;
#pragma unroll
    for (int j = 0; j < 6; ++j) mu += x[j];
    mu *= (1.f / 6.f);
    float var = 0.f;
#pragma unroll
    for (int j = 0; j < 6; ++j) { float d = x[j] - mu; var += d * d; }
    var *= (1.f / 6.f);
    float inv = rsqrtf(var + 1e-5f);
#pragma unroll
    for (int j = 0; j < 6; ++j) x[j] = (x[j] - mu) * inv * g[j] + b[j];
}

__global__ void pos_mlp_kernel(
    const float* __restrict__ W0, const float* __restrict__ B0,
    const float* __restrict__ G1, const float* __restrict__ Be1,
    const float* __restrict__ W1, const float* __restrict__ B1,
    const float* __restrict__ G2, const float* __restrict__ Be2,
    const float* __restrict__ W2, const float* __restrict__ B2,
    const float* __restrict__ G3, const float* __restrict__ Be3,
    const float* __restrict__ W3, const float* __restrict__ B3)
{
    int tid = threadIdx.x;
    int i = tid >> 6;
    int m = tid & 63;
    if (m >= NPOS || i >= 2) return;

    float bh = -7.f;
    float bw = (float)(m / 15) - 7.f;
    float bd = (float)(m % 15) - 7.f;

    float x[6], y[6];
#pragma unroll
    for (int j = 0; j < 6; ++j) {
        const float* w = W0 + (i * 6 + j) * 3;
        x[j] = bh * w[0] + bw * w[1] + bd * w[2] + B0[i * 6 + j];
    }
    ln6(x, G1 + i * 6, Be1 + i * 6);
#pragma unroll
    for (int j = 0; j < 6; ++j) x[j] = fmaxf(x[j], 0.f);
#pragma unroll
    for (int j = 0; j < 6; ++j) {
        const float* w = W1 + (i * 6 + j) * 6;
        float s = B1[i * 6 + j];
#pragma unroll
        for (int k = 0; k < 6; ++k) s += x[k] * w[k];
        y[j] = s;
    }
    ln6(y, G2 + i * 6, Be2 + i * 6);
#pragma unroll
    for (int j = 0; j < 6; ++j) y[j] = fmaxf(y[j], 0.f);
#pragma unroll
    for (int j = 0; j < 6; ++j) {
        const float* w = W2 + (i * 6 + j) * 6;
        float s = B2[i * 6 + j];
#pragma unroll
        for (int k = 0; k < 6; ++k) s += y[k] * w[k];
        x[j] = s;
    }
    ln6(x, G3 + i * 6, Be3 + i * 6);
#pragma unroll
    for (int j = 0; j < 6; ++j) x[j] = fmaxf(x[j], 0.f);
#pragma unroll
    for (int hh = 0; hh < NHEAD; ++hh) {
        const float* w = W3 + (i * NHEAD + hh) * 6;
        float s = B3[i * NHEAD + hh];
#pragma unroll
        for (int k = 0; k < 6; ++k) s += x[k] * w[k];
        g_pos[(i * NPOS + m) * NHEAD + hh] = s;
    }
}

// ---------------------------------------------------------------------------
// tf32 tensor-core fused attention.
// One CTA per (b,head), 256 threads = 8 warps. Warp w owns query rows
// [w*64, w*64+64). Streams over 64 key-blocks of 8 keys each:
//   S-frag = Q-frags @ K-frags (2 mmas/mtile), bias-add + ex2 in registers,
//   sum accumulate, quad-shuffle to P A-frags, O-frags += P @ V (2 mmas/mtile).
// K,V staged in smem pre-converted to tf32, in exact fragment order:
//   sKf[blk][ktile][reg][lane], sVf[blk][ntile][reg][lane]  (conflict-free LDS)
// ---------------------------------------------------------------------------
__global__ __launch_bounds__(256, 2) void attn_kernel(
    const float* __restrict__ Qg, int qb, int qh, int qt,
    const float* __restrict__ Kg, int kb, int kh, int kt,
    const float* __restrict__ Vg, int vb, int vh, int vt,
    float* __restrict__ Og, int ob, int oh, int ot,
    const float* __restrict__ posG)
{
    extern __shared__ float sm[];
    unsigned* sKf = (unsigned*)sm;            // 64*2*2*32 = 8192 words
    unsigned* sVf = (unsigned*)(sm + 8192);   // 8192 words
    float* sPos = sm + 16384;                 // 43 (+pad)

    int bh = blockIdx.x;
    int b = bh / NHEAD, h = bh % NHEAD;
    const float* Q = Qg + (long)b * qb + h * qh;
    const float* K = Kg + (long)b * kb + h * kh;
    const float* V = Vg + (long)b * vb + h * vh;
    float* O = Og + (long)b * ob + h * oh;

    int tid = threadIdx.x;
    if (tid < NPOS) sPos[tid] = posG[tid * NHEAD + h] * L2E;

    // ---- stage K,V -> tf32, fragment-ordered ----
    for (int e = tid; e < NTOK * 4; e += 256) {
        int key = e >> 2;
        int c4 = (e & 3) * 4;
        float4 kv = *reinterpret_cast<const float4*>(K + key * kt + c4);
        float4 vv = *reinterpret_cast<const float4*>(V + key * vt + c4);
        float kvj[4] = { kv.x, kv.y, kv.z, kv.w };
        float vvj[4] = { vv.x, vv.y, vv.z, vv.w };
        int blk = key >> 3;
#pragma unroll
        for (int j = 0; j < 4; ++j) {
            int kd = c4 + j;
            // K b-frag position: b[reg] = K[key][ ktile*8 + (lane&3) + 4*reg ], n = key&7 = lane>>2
            int ktile = kd >> 3, kreg = (kd >> 2) & 1;
            int kln = ((key & 7) << 2) | (kd & 3);
            sKf[((blk * 2 + ktile) * 2 + kreg) * 32 + kln] = f2tf32(kvj[j]);
            // V b-frag position: b[reg] = V[ (lane&3) + 4*reg ][ ntile*8 + lane>>2 ]
            int nt = kd >> 3, vreg = (key >> 2) & 1;
            int vln = ((kd & 7) << 2) | (key & 3);
            sVf[((blk * 2 + nt) * 2 + vreg) * 32 + vln] = f2tf32(vvj[j]);
        }
    }
    __syncthreads();

    int warp = tid >> 5, lane = tid & 31;
    int lq = lane >> 2;      // 0..7
    int lr = lane & 3;       // 0..3

    // ---- Q A-frags (resident): qa[mtile][ktile][reg] ----
    unsigned qa[4][2][4];
    int bb[4][2];            // bias base per (mtile, row-half): ds(row)+21-2*lr
#pragma unroll
    for (int mt = 0; mt < 4; ++mt) {
        int r0 = warp * 64 + mt * 16 + lq;
        int r1 = r0 + 8;
#pragma unroll
        for (int k2 = 0; k2 < 2; ++k2) {
            int kd0 = k2 * 8 + lr;
            qa[mt][k2][0] = f2tf32(Q[r0 * qt + kd0] * QS);
            qa[mt][k2][1] = f2tf32(Q[r1 * qt + kd0] * QS);
            qa[mt][k2][2] = f2tf32(Q[r0 * qt + kd0 + 4] * QS);
            qa[mt][k2][3] = f2tf32(Q[r1 * qt + kd0 + 4] * QS);
        }
        bb[mt][0] = ds9(r0) + 21 - 2 * lr;
        bb[mt][1] = ds9(r1) + 21 - 2 * lr;
    }

    float o[4][2][4];
#pragma unroll
    for (int mt = 0; mt < 4; ++mt)
#pragma unroll
        for (int nt = 0; nt < 2; ++nt)
#pragma unroll
            for (int j = 0; j < 4; ++j) o[mt][nt][j] = 0.f;
    float sumLo[4] = {0.f, 0.f, 0.f, 0.f};
    float sumHi[4] = {0.f, 0.f, 0.f, 0.f};

    int s_lo = (lane & ~3) | (lr >> 1);
    int s_hi = s_lo + 2;
    bool odd = (lr & 1);

    for (int blk = 0; blk < 64; ++blk) {
        const unsigned* kbp = sKf + blk * 128;
        const unsigned* vbp = sVf + blk * 128;
        unsigned kf[2][2], vf[2][2];
#pragma unroll
        for (int i = 0; i < 2; ++i) {
            kf[i][0] = kbp[(i * 2 + 0) * 32 + lane];
            kf[i][1] = kbp[(i * 2 + 1) * 32 + lane];
            vf[i][0] = vbp[(i * 2 + 0) * 32 + lane];
            vf[i][1] = vbp[(i * 2 + 1) * 32 + lane];
        }
        int dsb = (blk >> 3) + (blk & 7);

#pragma unroll
        for (int mt = 0; mt < 4; ++mt) {
            float s0 = 0.f, s1 = 0.f, s2 = 0.f, s3 = 0.f;
            mma_tf32(s0, s1, s2, s3,
                     qa[mt][0][0], qa[mt][0][1], qa[mt][0][2], qa[mt][0][3],
                     kf[0][0], kf[0][1]);
            mma_tf32(s0, s1, s2, s3,
                     qa[mt][1][0], qa[mt][1][1], qa[mt][1][2], qa[mt][1][3],
                     kf[1][0], kf[1][1]);

            int i0 = bb[mt][0] - dsb;
            int i1 = bb[mt][1] - dsb;
            float p0 = ex2(s0 + sPos[i0]);
            float p1 = ex2(s1 + sPos[i0 - 1]);
            float p2 = ex2(s2 + sPos[i1]);
            float p3 = ex2(s3 + sPos[i1 - 1]);
            sumLo[mt] += p0 + p1;
            sumHi[mt] += p2 + p3;

            // C-frag -> A-frag (P) via quad shuffles
            float v0 = __shfl_sync(0xffffffffu, p0, s_lo);
            float v1 = __shfl_sync(0xffffffffu, p1, s_lo);
            float v2 = __shfl_sync(0xffffffffu, p2, s_lo);
            float v3 = __shfl_sync(0xffffffffu, p3, s_lo);
            float w0 = __shfl_sync(0xffffffffu, p0, s_hi);
            float w1 = __shfl_sync(0xffffffffu, p1, s_hi);
            float w2 = __shfl_sync(0xffffffffu, p2, s_hi);
            float w3 = __shfl_sync(0xffffffffu, p3, s_hi);
            unsigned a0 = f2tf32(odd ? v1 : v0);
            unsigned a1 = f2tf32(odd ? v3 : v2);
            unsigned a2 = f2tf32(odd ? w1 : w0);
            unsigned a3 = f2tf32(odd ? w3 : w2);

            mma_tf32(o[mt][0][0], o[mt][0][1], o[mt][0][2], o[mt][0][3],
                     a0, a1, a2, a3, vf[0][0], vf[0][1]);
            mma_tf32(o[mt][1][0], o[mt][1][1], o[mt][1][2], o[mt][1][3],
                     a0, a1, a2, a3, vf[1][0], vf[1][1]);
        }
    }

    // quad-reduce row sums, normalize, store
#pragma unroll
    for (int mt = 0; mt < 4; ++mt) {
        float sl = sumLo[mt], sh = sumHi[mt];
        sl += __shfl_xor_sync(0xffffffffu, sl, 1);
        sl += __shfl_xor_sync(0xffffffffu, sl, 2);
        sh += __shfl_xor_sync(0xffffffffu, sh, 1);
        sh += __shfl_xor_sync(0xffffffffu, sh, 2);
        float invLo = 1.f / sl;
        float invHi = 1.f / sh;
        int r0 = warp * 64 + mt * 16 + lq;
        int r1 = r0 + 8;
#pragma unroll
        for (int nt = 0; nt < 2; ++nt) {
            int col = nt * 8 + 2 * lr;
            float2 wlo = make_float2(o[mt][nt][0] * invLo, o[mt][nt][1] * invLo);
            float2 whi = make_float2(o[mt][nt][2] * invHi, o[mt][nt][3] * invHi);
            *reinterpret_cast<float2*>(O + r0 * ot + col) = wlo;
            *reinterpret_cast<float2*>(O + r1 * ot + col) = whi;
        }
    }
}

// ---------------------------------------------------------------------------
extern "C" void kernel_launch(void* const* d_in, const int* in_sizes, int n_in,
                              void* d_out, int out_size)
{
    const float* qkv  = (const float*)d_in[0];   // (48,512,288)
    const float* grid = (const float*)d_in[1];   // (48,512,96)
    const float* W0  = (const float*)d_in[2];
    const float* B0  = (const float*)d_in[3];
    const float* G1  = (const float*)d_in[4];
    const float* Be1 = (const float*)d_in[5];
    const float* W1  = (const float*)d_in[6];
    const float* B1  = (const float*)d_in[7];
    const float* G2  = (const float*)d_in[8];
    const float* Be2 = (const float*)d_in[9];
    const float* W2  = (const float*)d_in[10];
    const float* B2  = (const float*)d_in[11];
    const float* G3  = (const float*)d_in[12];
    const float* Be3 = (const float*)d_in[13];
    const float* W3  = (const float*)d_in[14];
    const float* B3  = (const float*)d_in[15];
    float* out = (float*)d_out;

    float* pos_ptr = nullptr;
    float* x1_ptr = nullptr;
    cudaGetSymbolAddress((void**)&pos_ptr, g_pos);
    cudaGetSymbolAddress((void**)&x1_ptr, g_x1);

    const int SMEM = (16384 + 64) * sizeof(float);   // ~65.8 KB -> occ 2
    cudaFuncSetAttribute(attn_kernel, cudaFuncAttributeMaxDynamicSharedMemorySize, SMEM);

    pos_mlp_kernel<<<1, 128>>>(W0, B0, G1, Be1, W1, B1, G2, Be2, W2, B2, G3, Be3, W3, B3);

    // Pass 1: affine(grid, k, v, rpb0) -> g_x1 [b][h][t][16]
    attn_kernel<<<NB * NHEAD, 256, SMEM>>>(
        grid,          NTOK * 96,  HD, 96,            // Q = grid
        qkv + 96,      NTOK * 288, HD, 288,           // K = qkv[:, :, 96..]
        qkv + 192,     NTOK * 288, HD, 288,           // V = qkv[:, :, 192..]
        x1_ptr,        NHEAD * NTOK * HD, NTOK * HD, HD,
        pos_ptr);                                      // table 0

    // Pass 2: affine(q, grid, x1, rpb1) -> out (b, n, 96)
    attn_kernel<<<NB * NHEAD, 256, SMEM>>>(
        qkv,           NTOK * 288, HD, 288,           // Q = qkv[:, :, 0..]
        grid,          NTOK * 96,  HD, 96,            // K = grid
        x1_ptr,        NHEAD * NTOK * HD, NTOK * HD, HD,  // V = x1
        out,           NTOK * 96,  HD, 96,
        pos_ptr + NPOS * NHEAD);                       // table 1
}

// round 5
// speedup vs baseline: 10.8728x; 1.7834x over previous
#include <cuda_runtime.h>
#include <cuda_fp16.h>

// Problem constants: b=48, n=512, DIM=96, HEADS=6, hd=16, h=w=d=8
#define NB 48
#define NTOK 512
#define NHEAD 6
#define NPOS 43
#define L2E 1.4426950408889634f
#define QS (0.25f * L2E)     // attention scale folded with log2(e)

// ---------------------------------------------------------------------------
// helpers
// ---------------------------------------------------------------------------
__device__ __forceinline__ unsigned f2tf32(float x) {
    unsigned r; asm("cvt.rna.tf32.f32 %0,%1;" : "=r"(r) : "f"(x)); return r;
}
__device__ __forceinline__ float ex2(float x) {
    float r; asm("ex2.approx.ftz.f32 %0,%1;" : "=f"(r) : "f"(x)); return r;
}
__device__ __forceinline__ unsigned pkh(float lo, float hi) {   // f16x2 {lo,hi}
    unsigned d; asm("cvt.rn.f16x2.f32 %0,%1,%2;" : "=r"(d) : "f"(hi), "f"(lo)); return d;
}
__device__ __forceinline__ void mma_tf32(
    float& c0, float& c1, float& c2, float& c3,
    unsigned a0, unsigned a1, unsigned a2, unsigned a3,
    unsigned b0, unsigned b1)
{
    asm("mma.sync.aligned.m16n8k8.row.col.f32.tf32.tf32.f32 "
        "{%0,%1,%2,%3},{%4,%5,%6,%7},{%8,%9},{%0,%1,%2,%3};"
        : "+f"(c0), "+f"(c1), "+f"(c2), "+f"(c3)
        : "r"(a0), "r"(a1), "r"(a2), "r"(a3), "r"(b0), "r"(b1));
}
__device__ __forceinline__ void mma_f16(
    float& c0, float& c1, float& c2, float& c3,
    unsigned a0, unsigned a1, unsigned a2, unsigned a3,
    unsigned b0, unsigned b1)
{
    asm("mma.sync.aligned.m16n8k16.row.col.f32.f16.f16.f32 "
        "{%0,%1,%2,%3},{%4,%5,%6,%7},{%8,%9},{%0,%1,%2,%3};"
        : "+f"(c0), "+f"(c1), "+f"(c2), "+f"(c3)
        : "r"(a0), "r"(a1), "r"(a2), "r"(a3), "r"(b0), "r"(b1));
}
__device__ __forceinline__ int ds9(int t) {   // base-8 digit sum, t < 512
    return (t >> 6) + ((t >> 3) & 7) + (t & 7);
}

// smem word offsets
#define SK1 0
#define SV1 8192
#define SK2 12288
#define SV2 20480
#define SP1 24576
#define SP2 24624
#define SMEM_WORDS 24672

// ---------------------------------------------------------------------------
// attention core: 32 blocks of 16 keys; S = Q@K^T (tf32), P=ex2(S+bias),
// O += P@V (fp16 k16, A-frag = S C-frag -> no shuffles).
// ---------------------------------------------------------------------------
__device__ __forceinline__ void attn_core(
    const float* __restrict__ Qp, int qt,
    const unsigned* __restrict__ sK, const unsigned* __restrict__ sV,
    const float* __restrict__ sPos,
    int warp, int lane, const int bb[4][2],
    float o[4][2][4], float sL[4], float sH[4])
{
    int lq = lane >> 2, lr = lane & 3;

    unsigned qa[4][2][4];
#pragma unroll
    for (int mt = 0; mt < 4; ++mt) {
        int r0 = warp * 64 + mt * 16 + lq, r1 = r0 + 8;
#pragma unroll
        for (int ks = 0; ks < 2; ++ks) {
            int k0 = ks * 8 + lr;
            qa[mt][ks][0] = f2tf32(Qp[r0 * qt + k0] * QS);
            qa[mt][ks][1] = f2tf32(Qp[r1 * qt + k0] * QS);
            qa[mt][ks][2] = f2tf32(Qp[r0 * qt + k0 + 4] * QS);
            qa[mt][ks][3] = f2tf32(Qp[r1 * qt + k0 + 4] * QS);
        }
    }
#pragma unroll
    for (int mt = 0; mt < 4; ++mt) {
        sL[mt] = 0.f; sH[mt] = 0.f;
#pragma unroll
        for (int nt = 0; nt < 2; ++nt)
#pragma unroll
            for (int j = 0; j < 4; ++j) o[mt][nt][j] = 0.f;
    }

    for (int blk = 0; blk < 32; ++blk) {
        uint2 k00 = *(const uint2*)(sK + ((blk * 2 + 0) * 2 + 0) * 64 + lane * 2);
        uint2 k01 = *(const uint2*)(sK + ((blk * 2 + 0) * 2 + 1) * 64 + lane * 2);
        uint2 k10 = *(const uint2*)(sK + ((blk * 2 + 1) * 2 + 0) * 64 + lane * 2);
        uint2 k11 = *(const uint2*)(sK + ((blk * 2 + 1) * 2 + 1) * 64 + lane * 2);
        uint2 v0  = *(const uint2*)(sV + (blk * 2 + 0) * 64 + lane * 2);
        uint2 v1  = *(const uint2*)(sV + (blk * 2 + 1) * 64 + lane * 2);
        int tb = 2 * blk;
        int dsb = (tb >> 3) + (tb & 7);

#pragma unroll
        for (int mt = 0; mt < 4; ++mt) {
            float c0 = 0.f, c1 = 0.f, c2 = 0.f, c3 = 0.f;
            float d0 = 0.f, d1 = 0.f, d2 = 0.f, d3 = 0.f;
            mma_tf32(c0, c1, c2, c3, qa[mt][0][0], qa[mt][0][1], qa[mt][0][2], qa[mt][0][3], k00.x, k00.y);
            mma_tf32(c0, c1, c2, c3, qa[mt][1][0], qa[mt][1][1], qa[mt][1][2], qa[mt][1][3], k01.x, k01.y);
            mma_tf32(d0, d1, d2, d3, qa[mt][0][0], qa[mt][0][1], qa[mt][0][2], qa[mt][0][3], k10.x, k10.y);
            mma_tf32(d0, d1, d2, d3, qa[mt][1][0], qa[mt][1][1], qa[mt][1][2], qa[mt][1][3], k11.x, k11.y);

            int i0 = bb[mt][0] - dsb;
            int i1 = bb[mt][1] - dsb;
            // cols: nt0 = {2lr, 2lr+1} (idx i-0, i-1); nt1 = {8+2lr, 8+2lr+1} (idx i-1, i-2)
            float p00 = ex2(c0 + sPos[i0]);
            float p01 = ex2(c1 + sPos[i0 - 1]);
            float p02 = ex2(c2 + sPos[i1]);
            float p03 = ex2(c3 + sPos[i1 - 1]);
            float p10 = ex2(d0 + sPos[i0 - 1]);
            float p11 = ex2(d1 + sPos[i0 - 2]);
            float p12 = ex2(d2 + sPos[i1 - 1]);
            float p13 = ex2(d3 + sPos[i1 - 2]);
            sL[mt] += (p00 + p01) + (p10 + p11);
            sH[mt] += (p02 + p03) + (p12 + p13);

            unsigned a0 = pkh(p00, p01);   // row lq,   keys 2lr,2lr+1
            unsigned a1 = pkh(p02, p03);   // row lq+8, keys 2lr,2lr+1
            unsigned a2 = pkh(p10, p11);   // row lq,   keys 2lr+8,2lr+9
            unsigned a3 = pkh(p12, p13);   // row lq+8, keys 2lr+8,2lr+9
            mma_f16(o[mt][0][0], o[mt][0][1], o[mt][0][2], o[mt][0][3], a0, a1, a2, a3, v0.x, v0.y);
            mma_f16(o[mt][1][0], o[mt][1][1], o[mt][1][2], o[mt][1][3], a0, a1, a2, a3, v1.x, v1.y);
        }
    }
}

// ---------------------------------------------------------------------------
// Fully fused kernel: one CTA per (b,head); stages K1/V1/K2, computes its own
// bias tables, runs pass 1 into smem (fp16 V-frag layout), then pass 2 to out.
// ---------------------------------------------------------------------------
__global__ __launch_bounds__(256, 2) void fused_kernel(
    const float* __restrict__ qkv, const float* __restrict__ grid,
    const float* __restrict__ W0, const float* __restrict__ B0,
    const float* __restrict__ G1, const float* __restrict__ Be1,
    const float* __restrict__ W1, const float* __restrict__ B1,
    const float* __restrict__ G2, const float* __restrict__ Be2,
    const float* __restrict__ W2, const float* __restrict__ B2,
    const float* __restrict__ G3, const float* __restrict__ Be3,
    const float* __restrict__ W3, const float* __restrict__ B3,
    float* __restrict__ out)
{
    extern __shared__ float sm[];
    unsigned* sK1 = (unsigned*)(sm + SK1);
    unsigned* sV1 = (unsigned*)(sm + SV1);
    unsigned* sK2 = (unsigned*)(sm + SK2);
    unsigned* sV2 = (unsigned*)(sm + SV2);
    float* sPos1 = sm + SP1;
    float* sPos2 = sm + SP2;

    int bh = blockIdx.x;
    int b = bh / NHEAD, h = bh % NHEAD;
    const float* qkvB = qkv + (long)b * NTOK * 288;
    const float* gridB = grid + (long)b * NTOK * 96;

    int tid = threadIdx.x;

    // ---- stage K1 (qkv k-part, tf32 frags), V1 (qkv v-part, fp16 frags),
    //      K2 (grid, tf32 frags) ----
    for (int e = tid; e < NTOK * 4; e += 256) {
        int key = e >> 2;
        int c4 = (e & 3) * 4;
        float4 kv = *(const float4*)(qkvB + key * 288 + 96 + h * 16 + c4);
        float4 vv = *(const float4*)(qkvB + key * 288 + 192 + h * 16 + c4);
        float4 gv = *(const float4*)(gridB + key * 96 + h * 16 + c4);
        float kj[4] = { kv.x, kv.y, kv.z, kv.w };
        float vj[4] = { vv.x, vv.y, vv.z, vv.w };
        float gj[4] = { gv.x, gv.y, gv.z, gv.w };
        int blk = key >> 4, kb = key & 15;
        int ntK = kb >> 3, lqK = kb & 7;
        int regV = kb >> 3, kpv = kb & 7, lrV = kpv >> 1, hfV = kpv & 1;
#pragma unroll
        for (int j = 0; j < 4; ++j) {
            int dim = c4 + j;
            int ks = dim >> 3, kk = dim & 7, lr = kk & 3, r = kk >> 2;
            int w = ((blk * 2 + ntK) * 2 + ks) * 64 + (lqK * 4 + lr) * 2 + r;
            sK1[w] = f2tf32(kj[j]);
            sK2[w] = f2tf32(gj[j]);
            int wv = (blk * 2 + (dim >> 3)) * 64 + ((dim & 7) * 4 + lrV) * 2 + regV;
            ((__half*)sV2)[0];  // no-op to keep type visible
            ((__half*)sV1)[wv * 2 + hfV] = __float2half_rn(vj[j]);
        }
    }

    // ---- inline pos-MLP: threads 0..85 compute the two 43-row tables ----
    if (tid < 86) {
        int i = (tid >= NPOS) ? 1 : 0;
        int m = tid - i * NPOS;
        float bh_ = -7.f;
        float bw_ = (float)(m / 15) - 7.f;
        float bd_ = (float)(m % 15) - 7.f;
        float x[6], y[6];
#pragma unroll
        for (int j = 0; j < 6; ++j) {
            const float* w = W0 + (i * 6 + j) * 3;
            x[j] = bh_ * w[0] + bw_ * w[1] + bd_ * w[2] + B0[i * 6 + j];
        }
        // LN1 + relu + lin1
        {
            float mu = 0.f;
#pragma unroll
            for (int j = 0; j < 6; ++j) mu += x[j];
            mu *= (1.f / 6.f);
            float var = 0.f;
#pragma unroll
            for (int j = 0; j < 6; ++j) { float d = x[j] - mu; var += d * d; }
            float inv = rsqrtf(var * (1.f / 6.f) + 1e-5f);
#pragma unroll
            for (int j = 0; j < 6; ++j)
                x[j] = fmaxf((x[j] - mu) * inv * G1[i * 6 + j] + Be1[i * 6 + j], 0.f);
#pragma unroll
            for (int j = 0; j < 6; ++j) {
                const float* w = W1 + (i * 6 + j) * 6;
                float s = B1[i * 6 + j];
#pragma unroll
                for (int k = 0; k < 6; ++k) s += x[k] * w[k];
                y[j] = s;
            }
        }
        // LN2 + relu + lin2
        {
            float mu = 0.f;
#pragma unroll
            for (int j = 0; j < 6; ++j) mu += y[j];
            mu *= (1.f / 6.f);
            float var = 0.f;
#pragma unroll
            for (int j = 0; j < 6; ++j) { float d = y[j] - mu; var += d * d; }
            float inv = rsqrtf(var * (1.f / 6.f) + 1e-5f);
#pragma unroll
            for (int j = 0; j < 6; ++j)
                y[j] = fmaxf((y[j] - mu) * inv * G2[i * 6 + j] + Be2[i * 6 + j], 0.f);
#pragma unroll
            for (int j = 0; j < 6; ++j) {
                const float* w = W2 + (i * 6 + j) * 6;
                float s = B2[i * 6 + j];
#pragma unroll
                for (int k = 0; k < 6; ++k) s += y[k] * w[k];
                x[j] = s;
            }
        }
        // LN3 + relu + lin3 (head h only)
        {
            float mu = 0.f;
#pragma unroll
            for (int j = 0; j < 6; ++j) mu += x[j];
            mu *= (1.f / 6.f);
            float var = 0.f;
#pragma unroll
            for (int j = 0; j < 6; ++j) { float d = x[j] - mu; var += d * d; }
            float inv = rsqrtf(var * (1.f / 6.f) + 1e-5f);
#pragma unroll
            for (int j = 0; j < 6; ++j)
                x[j] = fmaxf((x[j] - mu) * inv * G3[i * 6 + j] + Be3[i * 6 + j], 0.f);
            const float* w = W3 + (i * NHEAD + h) * 6;
            float s = B3[i * NHEAD + h];
#pragma unroll
            for (int k = 0; k < 6; ++k) s += x[k] * w[k];
            ((i == 0) ? sPos1 : sPos2)[m] = s * L2E;
        }
    }
    __syncthreads();

    int warp = tid >> 5, lane = tid & 31, lq = lane >> 2, lr = lane & 3;
    int bb[4][2];
#pragma unroll
    for (int mt = 0; mt < 4; ++mt) {
        int r0 = warp * 64 + mt * 16 + lq;
        bb[mt][0] = ds9(r0) + 21 - 2 * lr;
        bb[mt][1] = ds9(r0 + 8) + 21 - 2 * lr;
    }

    float o[4][2][4], sL[4], sH[4];

    // ================= PASS 1: Q=grid, K=qkv.k, V=qkv.v =================
    attn_core(gridB + h * 16, 96, sK1, sV1, sPos1, warp, lane, bb, o, sL, sH);

    // normalize and write x1 into sV2 (fp16 V-fragment layout; keys = rows)
#pragma unroll
    for (int mt = 0; mt < 4; ++mt) {
        float sl = sL[mt], sh = sH[mt];
        sl += __shfl_xor_sync(0xffffffffu, sl, 1);
        sl += __shfl_xor_sync(0xffffffffu, sl, 2);
        sh += __shfl_xor_sync(0xffffffffu, sh, 1);
        sh += __shfl_xor_sync(0xffffffffu, sh, 2);
        float il = 1.f / sl, ih = 1.f / sh;
        int r0 = warp * 64 + mt * 16 + lq;
#pragma unroll
        for (int nt = 0; nt < 2; ++nt) {
#pragma unroll
            for (int j = 0; j < 4; ++j) {
                float val = o[mt][nt][j] * ((j < 2) ? il : ih);
                int row = (j < 2) ? r0 : (r0 + 8);
                int col = nt * 8 + 2 * lr + (j & 1);
                int blk = row >> 4, kb = row & 15;
                int reg = kb >> 3, kp2 = kb & 7, lrv = kp2 >> 1, hf = kp2 & 1;
                int w = (blk * 2 + nt) * 64 + ((col & 7) * 4 + lrv) * 2 + reg;
                ((__half*)sV2)[w * 2 + hf] = __float2half_rn(val);
            }
        }
    }
    __syncthreads();

    // ================= PASS 2: Q=qkv.q, K=grid, V=x1 =================
    attn_core(qkvB + h * 16, 288, sK2, sV2, sPos2, warp, lane, bb, o, sL, sH);

    float* O = out + (long)b * NTOK * 96 + h * 16;
#pragma unroll
    for (int mt = 0; mt < 4; ++mt) {
        float sl = sL[mt], sh = sH[mt];
        sl += __shfl_xor_sync(0xffffffffu, sl, 1);
        sl += __shfl_xor_sync(0xffffffffu, sl, 2);
        sh += __shfl_xor_sync(0xffffffffu, sh, 1);
        sh += __shfl_xor_sync(0xffffffffu, sh, 2);
        float il = 1.f / sl, ih = 1.f / sh;
        int r0 = warp * 64 + mt * 16 + lq, r1 = r0 + 8;
#pragma unroll
        for (int nt = 0; nt < 2; ++nt) {
            int col = nt * 8 + 2 * lr;
            *(float2*)(O + r0 * 96 + col) = make_float2(o[mt][nt][0] * il, o[mt][nt][1] * il);
            *(float2*)(O + r1 * 96 + col) = make_float2(o[mt][nt][2] * ih, o[mt][nt][3] * ih);
        }
    }
}

// ---------------------------------------------------------------------------
extern "C" void kernel_launch(void* const* d_in, const int* in_sizes, int n_in,
                              void* d_out, int out_size)
{
    const float* qkv  = (const float*)d_in[0];
    const float* grid = (const float*)d_in[1];
    const float* W0  = (const float*)d_in[2];
    const float* B0  = (const float*)d_in[3];
    const float* G1  = (const float*)d_in[4];
    const float* Be1 = (const float*)d_in[5];
    const float* W1  = (const float*)d_in[6];
    const float* B1  = (const float*)d_in[7];
    const float* G2  = (const float*)d_in[8];
    const float* Be2 = (const float*)d_in[9];
    const float* W2  = (const float*)d_in[10];
    const float* B2  = (const float*)d_in[11];
    const float* G3  = (const float*)d_in[12];
    const float* Be3 = (const float*)d_in[13];
    const float* W3  = (const float*)d_in[14];
    const float* B3  = (const float*)d_in[15];
    float* out = (float*)d_out;

    const int SMEM = SMEM_WORDS * sizeof(float);   // ~96.4 KB -> 2 CTA/SM
    cudaFuncSetAttribute(fused_kernel, cudaFuncAttributeMaxDynamicSharedMemorySize, SMEM);

    fused_kernel<<<NB * NHEAD, 256, SMEM>>>(
        qkv, grid, W0, B0, G1, Be1, W1, B1, G2, Be2, W2, B2, G3, Be3, W3, B3, out);
}